// round 2
// baseline (speedup 1.0000x reference)
#include <cuda_runtime.h>
#include <math.h>

// Shapes (fixed for this problem)
//  h_enc: [16, 2048, 1024] f32
//  h_dec: [64, 16, 1024]   f32
//  W_psi: [1024,1024], b_psi:[1024], W_phi:[1024,1024], b_phi:[1024]
//  out:   [16, 64, 1024]   f32
//
// Restructured math (psi never materialized):
//  phi[i,a] = sum_h h_dec[i,h] * W_phi[a,h] + b_phi[a]    (i = q*16+b)
//  M[i,h]   = sum_a phi[i,a] * W_psi[a,h]
//  s[i]     = sum_a phi[i,a] * b_psi[a]
//  e[b,t,q] = h_enc[b,t,:] . M[q*16+b,:] + s[q*16+b]
//  a = softmax_t(e);  out[b,q,h] = sum_t a[b,t,q] * h_enc[b,t,h]

#define B_DIM 16
#define T_DIM 2048
#define Q_DIM 64
#define H_DIM 1024
#define A_DIM 1024
#define QB_DIM 1024
#define SPLITS 16
#define TCHUNK 128   // T_DIM / SPLITS

static_assert(T_DIM == SPLITS * TCHUNK, "split layout");

// Scratch (static device memory; no runtime allocation)
__device__ float g_phi[QB_DIM * A_DIM];                       // 4 MB
__device__ float g_M[QB_DIM * H_DIM];                         // 4 MB
__device__ float g_s[QB_DIM];
__device__ float g_cpart[B_DIM * SPLITS * Q_DIM * H_DIM];     // 64 MB
__device__ float g_mpart[B_DIM * SPLITS * Q_DIM];
__device__ float g_lpart[B_DIM * SPLITS * Q_DIM];

// ---------------------------------------------------------------------------
// Generic 64x64x32-tiled fp32 GEMM, 128 threads, 8x4 per thread.
// TRANS_W = true : C[M,N] = X[M,K] @ W[N,K]^T  (+bias over N)
// TRANS_W = false: C[M,N] = X[M,K] @ W[K,N]    (+bias over N)
// ---------------------------------------------------------------------------
template <bool TRANS_W>
__global__ void __launch_bounds__(128) gemm64(
    const float* __restrict__ X, const float* __restrict__ W,
    const float* __restrict__ bias, float* __restrict__ C,
    int K, int N)
{
    __shared__ float Xs[64 * 33];   // [row][kk]
    __shared__ float Ws[32 * 65];   // [kk][col]
    const int tid = threadIdx.x;
    const int tx = tid & 15;        // 16 -> N (interleaved stride 16)
    const int ty = tid >> 4;        // 8  -> M (8 rows each)
    const int row0 = blockIdx.y * 64;
    const int col0 = blockIdx.x * 64;

    float acc[8][4];
#pragma unroll
    for (int i = 0; i < 8; i++)
#pragma unroll
        for (int j = 0; j < 4; j++) acc[i][j] = 0.f;

    for (int k0 = 0; k0 < K; k0 += 32) {
        // Load X tile 64x32 (512 float4)
#pragma unroll
        for (int l = 0; l < 4; l++) {
            int idx = tid + l * 128;
            int r = idx >> 3, c = (idx & 7) * 4;
            float4 v = *(const float4*)(X + (size_t)(row0 + r) * K + k0 + c);
            Xs[r * 33 + c + 0] = v.x; Xs[r * 33 + c + 1] = v.y;
            Xs[r * 33 + c + 2] = v.z; Xs[r * 33 + c + 3] = v.w;
        }
        if (TRANS_W) {
            // W rows are output columns; transpose into Ws[kk][col]
#pragma unroll
            for (int l = 0; l < 4; l++) {
                int idx = tid + l * 128;
                int r = idx >> 3, c = (idx & 7) * 4;   // r: col(a), c: kk
                float4 v = *(const float4*)(W + (size_t)(col0 + r) * K + k0 + c);
                Ws[(c + 0) * 65 + r] = v.x; Ws[(c + 1) * 65 + r] = v.y;
                Ws[(c + 2) * 65 + r] = v.z; Ws[(c + 3) * 65 + r] = v.w;
            }
        } else {
            // W tile rows are kk already
#pragma unroll
            for (int l = 0; l < 4; l++) {
                int idx = tid + l * 128;
                int r = idx >> 4, c = (idx & 15) * 4;  // r: kk, c: col
                float4 v = *(const float4*)(W + (size_t)(k0 + r) * N + col0 + c);
                Ws[r * 65 + c + 0] = v.x; Ws[r * 65 + c + 1] = v.y;
                Ws[r * 65 + c + 2] = v.z; Ws[r * 65 + c + 3] = v.w;
            }
        }
        __syncthreads();
#pragma unroll
        for (int kk = 0; kk < 32; kk++) {
            float a[8], bb[4];
#pragma unroll
            for (int i = 0; i < 8; i++) a[i] = Xs[(ty * 8 + i) * 33 + kk];
#pragma unroll
            for (int j = 0; j < 4; j++) bb[j] = Ws[kk * 65 + tx + 16 * j];
#pragma unroll
            for (int i = 0; i < 8; i++)
#pragma unroll
                for (int j = 0; j < 4; j++) acc[i][j] += a[i] * bb[j];
        }
        __syncthreads();
    }

#pragma unroll
    for (int j = 0; j < 4; j++) {
        int cc = col0 + tx + 16 * j;
        float bv = bias ? bias[cc] : 0.f;
#pragma unroll
        for (int i = 0; i < 8; i++)
            C[(size_t)(row0 + ty * 8 + i) * N + cc] = acc[i][j] + bv;
    }
}

// s[i] = phi[i,:] . b_psi
__global__ void __launch_bounds__(256) dot_s_kernel(const float* __restrict__ phi,
                                                    const float* __restrict__ bpsi,
                                                    float* __restrict__ s)
{
    int i = blockIdx.x;
    float p = 0.f;
    for (int a = threadIdx.x; a < A_DIM; a += 256)
        p += phi[(size_t)i * A_DIM + a] * bpsi[a];
    __shared__ float r[8];
#pragma unroll
    for (int o = 16; o; o >>= 1) p += __shfl_down_sync(0xffffffffu, p, o);
    if ((threadIdx.x & 31) == 0) r[threadIdx.x >> 5] = p;
    __syncthreads();
    if (threadIdx.x == 0) {
        float t = 0.f;
#pragma unroll
        for (int w = 0; w < 8; w++) t += r[w];
        s[i] = t;
    }
}

// ---------------------------------------------------------------------------
// Fused attention chunk: for (b, split) compute e-tile [128 t x 64 q],
// local softmax stats, p = exp(e - m), c_part[64 q x 1024 h] = p^T @ h_tile.
// 256 threads. Dynamic smem layout (floats):
//   [0      .. 16896)  union: phase1 {hs1[128*33] @0, Msk[32*65] @4224}
//                             phase2 {hs2[128*132]}
//   [16896  .. 25216)  ps[128*65]
//   [25216  .. 26304)  red[64*17]
//   [26304  .. 26368)  sv[64]  (s bias, later reused as per-q max)
// ---------------------------------------------------------------------------
#define SMEM_FLOATS 26368
#define ATTN_SMEM_BYTES (SMEM_FLOATS * 4)

__global__ void __launch_bounds__(256, 2) attn_chunk_kernel(
    const float* __restrict__ h_enc)
{
    const int split = blockIdx.x;   // 0..15
    const int b = blockIdx.y;       // 0..15
    const int t0 = split * TCHUNK;
    const int tid = threadIdx.x;
    const int tx = tid & 15;
    const int ty = tid >> 4;

    extern __shared__ float sm[];
    float* hs1 = sm;                 // [128][33]
    float* Msk = sm + 128 * 33;      // [32][65]
    float* hs2 = sm;                 // [128][132] (union with hs1/Msk)
    float* ps  = sm + 16896;         // [128][65]
    float* red = sm + 25216;         // [64][17]
    float* sv  = sm + 26304;         // [64]

    const float* hb = h_enc + ((size_t)b * T_DIM + t0) * H_DIM;

    if (tid < 64) sv[tid] = g_s[tid * B_DIM + b];

    // -------- Phase 1: e[128 t][64 q] = h_tile @ M_b^T --------
    float e[8][4];
#pragma unroll
    for (int i = 0; i < 8; i++)
#pragma unroll
        for (int j = 0; j < 4; j++) e[i][j] = 0.f;

    for (int k0 = 0; k0 < H_DIM; k0 += 32) {
        // hs1: 128x32 floats = 1024 float4, 4 per thread
#pragma unroll
        for (int l = 0; l < 4; l++) {
            int idx = tid + l * 256;
            int r = idx >> 3, c = (idx & 7) * 4;
            float4 v = *(const float4*)(hb + (size_t)r * H_DIM + k0 + c);
            hs1[r * 33 + c + 0] = v.x; hs1[r * 33 + c + 1] = v.y;
            hs1[r * 33 + c + 2] = v.z; hs1[r * 33 + c + 3] = v.w;
        }
        // Msk: 64q x 32k transposed into [kk][q]; 8 floats per thread
        {
            int q = tid >> 2, kb = (tid & 3) * 8;
            const float* mp = g_M + (size_t)(q * B_DIM + b) * H_DIM + k0 + kb;
            float4 v0 = *(const float4*)mp;
            float4 v1 = *(const float4*)(mp + 4);
            Msk[(kb + 0) * 65 + q] = v0.x; Msk[(kb + 1) * 65 + q] = v0.y;
            Msk[(kb + 2) * 65 + q] = v0.z; Msk[(kb + 3) * 65 + q] = v0.w;
            Msk[(kb + 4) * 65 + q] = v1.x; Msk[(kb + 5) * 65 + q] = v1.y;
            Msk[(kb + 6) * 65 + q] = v1.z; Msk[(kb + 7) * 65 + q] = v1.w;
        }
        __syncthreads();
#pragma unroll
        for (int kk = 0; kk < 32; kk++) {
            float a[8], bb[4];
#pragma unroll
            for (int i = 0; i < 8; i++) a[i] = hs1[(ty * 8 + i) * 33 + kk];
#pragma unroll
            for (int j = 0; j < 4; j++) bb[j] = Msk[kk * 65 + tx + 16 * j];
#pragma unroll
            for (int i = 0; i < 8; i++)
#pragma unroll
                for (int j = 0; j < 4; j++) e[i][j] += a[i] * bb[j];
        }
        __syncthreads();
    }

    // Add s bias, local max per q
#pragma unroll
    for (int j = 0; j < 4; j++) {
        int q = tx + 16 * j;
        float sb = sv[q];
        float mloc = -1e30f;
#pragma unroll
        for (int i = 0; i < 8; i++) {
            e[i][j] += sb;
            mloc = fmaxf(mloc, e[i][j]);
        }
        red[q * 17 + ty] = mloc;
    }
    __syncthreads();
    if (tid < 64) {
        float m = -1e30f;
#pragma unroll
        for (int w = 0; w < 16; w++) m = fmaxf(m, red[tid * 17 + w]);
        sv[tid] = m;   // reuse sv as per-q chunk max
    }
    __syncthreads();

    // p = exp(e - m), write into ps, accumulate l
    float lloc[4];
#pragma unroll
    for (int j = 0; j < 4; j++) {
        int q = tx + 16 * j;
        float m = sv[q];
        float sum = 0.f;
#pragma unroll
        for (int i = 0; i < 8; i++) {
            float p = __expf(e[i][j] - m);
            ps[(ty * 8 + i) * 65 + q] = p;
            sum += p;
        }
        lloc[j] = sum;
    }
    __syncthreads();   // ensure max reads done before red overwrite
#pragma unroll
    for (int j = 0; j < 4; j++) red[(tx + 16 * j) * 17 + ty] = lloc[j];
    __syncthreads();
    if (tid < 64) {
        float l = 0.f;
#pragma unroll
        for (int w = 0; w < 16; w++) l += red[tid * 17 + w];
        int base = (b * SPLITS + split) * Q_DIM + tid;
        g_lpart[base] = l;
        g_mpart[base] = sv[tid];
    }

    // -------- Phase 2: c_part[64 q][1024 h] = p^T @ h_tile --------
    float* cp = g_cpart + (size_t)(b * SPLITS + split) * Q_DIM * H_DIM;
    for (int h0 = 0; h0 < H_DIM; h0 += 128) {
        __syncthreads();   // previous hs2 consumers done / ps ready
        // load hs2[128][132] : 4096 float4, 16 per thread
#pragma unroll
        for (int l = 0; l < 16; l++) {
            int idx = tid + l * 256;
            int r = idx >> 5, c = (idx & 31) * 4;
            float4 v = *(const float4*)(hb + (size_t)r * H_DIM + h0 + c);
            *(float4*)(hs2 + r * 132 + c) = v;
        }
        __syncthreads();
        float acc[4][8];
#pragma unroll
        for (int j = 0; j < 4; j++)
#pragma unroll
            for (int u = 0; u < 8; u++) acc[j][u] = 0.f;
#pragma unroll 8
        for (int kk = 0; kk < 128; kk++) {
            float a[4], bb[8];
#pragma unroll
            for (int j = 0; j < 4; j++) a[j] = ps[kk * 65 + ty * 4 + j];
#pragma unroll
            for (int u = 0; u < 8; u++) bb[u] = hs2[kk * 132 + tx + 16 * u];
#pragma unroll
            for (int j = 0; j < 4; j++)
#pragma unroll
                for (int u = 0; u < 8; u++) acc[j][u] += a[j] * bb[u];
        }
#pragma unroll
        for (int j = 0; j < 4; j++) {
            int q = ty * 4 + j;
#pragma unroll
            for (int u = 0; u < 8; u++)
                cp[(size_t)q * H_DIM + h0 + tx + 16 * u] = acc[j][u];
        }
    }
}

// Combine split partials: out[b,q,h] = sum_s w_s * cpart_s[q,h] / (sum_s w_s * l_s)
__global__ void __launch_bounds__(256) combine_kernel(float* __restrict__ out)
{
    const int q = blockIdx.x;   // 64
    const int b = blockIdx.y;   // 16
    const int tid = threadIdx.x;

    float m = -1e30f;
#pragma unroll
    for (int sI = 0; sI < SPLITS; sI++)
        m = fmaxf(m, g_mpart[(b * SPLITS + sI) * Q_DIM + q]);
    float w[SPLITS];
    float l = 0.f;
#pragma unroll
    for (int sI = 0; sI < SPLITS; sI++) {
        float ws = __expf(g_mpart[(b * SPLITS + sI) * Q_DIM + q] - m);
        w[sI] = ws;
        l += ws * g_lpart[(b * SPLITS + sI) * Q_DIM + q];
    }
    float inv = 1.0f / l;

    for (int h = tid; h < H_DIM; h += 256) {
        float acc = 0.f;
#pragma unroll
        for (int sI = 0; sI < SPLITS; sI++)
            acc += w[sI] * g_cpart[((size_t)(b * SPLITS + sI) * Q_DIM + q) * H_DIM + h];
        out[((size_t)(b * Q_DIM + q)) * H_DIM + h] = acc * inv;
    }
}

// ---------------------------------------------------------------------------
extern "C" void kernel_launch(void* const* d_in, const int* in_sizes, int n_in,
                              void* d_out, int out_size)
{
    (void)in_sizes; (void)n_in; (void)out_size;
    const float* h_enc = (const float*)d_in[0];
    const float* h_dec = (const float*)d_in[1];
    const float* W_psi = (const float*)d_in[2];
    const float* b_psi = (const float*)d_in[3];
    const float* W_phi = (const float*)d_in[4];
    const float* b_phi = (const float*)d_in[5];
    float* out = (float*)d_out;

    float *phi, *Mmat, *s;
    cudaGetSymbolAddress((void**)&phi, g_phi);
    cudaGetSymbolAddress((void**)&Mmat, g_M);
    cudaGetSymbolAddress((void**)&s, g_s);

    // phi = h_dec @ W_phi^T + b_phi   (NT)
    gemm64<true><<<dim3(16, 16), 128>>>(h_dec, W_phi, b_phi, phi, H_DIM, A_DIM);
    // M = phi @ W_psi                 (NN)
    gemm64<false><<<dim3(16, 16), 128>>>(phi, W_psi, nullptr, Mmat, A_DIM, H_DIM);
    // s = phi @ b_psi
    dot_s_kernel<<<QB_DIM, 256>>>(phi, b_psi, s);

    // Fused split-T attention
    cudaFuncSetAttribute(attn_chunk_kernel,
                         cudaFuncAttributeMaxDynamicSharedMemorySize,
                         ATTN_SMEM_BYTES);
    attn_chunk_kernel<<<dim3(SPLITS, B_DIM), 256, ATTN_SMEM_BYTES>>>(h_enc);

    // Combine partials
    combine_kernel<<<dim3(Q_DIM, B_DIM), 256>>>(out);
}

// round 4
// speedup vs baseline: 1.0339x; 1.0339x over previous
#include <cuda_runtime.h>
#include <math.h>

// Shapes (fixed):
//  h_enc: [16, 2048, 1024] f32 ; h_dec: [64, 16, 1024] f32
//  W_psi/W_phi: [1024,1024] ; b_psi/b_phi: [1024] ; out: [16, 64, 1024] f32
//
// Restructured math (psi never materialized):
//  phi[i,a] = sum_h h_dec[i,h]*W_phi[a,h] + b_phi[a]   (i = q*16+b)
//  M[i,h]   = sum_a phi[i,a]*W_psi[a,h]
//  s[i]     = sum_a phi[i,a]*b_psi[a]
//  e[b,t,q] = h_enc[b,t,:] . M[q*16+b,:] + s[q*16+b]
//  a = softmax_t(e);  out[b,q,h] = sum_t a[b,t,q]*h_enc[b,t,h]

#define B_DIM 16
#define T_DIM 2048
#define Q_DIM 64
#define H_DIM 1024
#define A_DIM 1024
#define QB_DIM 1024
#define SPLITS 16
#define TCHUNK 128

static_assert(T_DIM == SPLITS * TCHUNK, "split layout");

__device__ float g_phi[QB_DIM * A_DIM];
__device__ float g_M[QB_DIM * H_DIM];
__device__ float g_s[QB_DIM];
__device__ float g_cpart[B_DIM * SPLITS * Q_DIM * H_DIM];
__device__ float g_mpart[B_DIM * SPLITS * Q_DIM];
__device__ float g_lpart[B_DIM * SPLITS * Q_DIM];

typedef unsigned long long u64;

__device__ __forceinline__ u64 ffma2(u64 a, u64 b, u64 c) {
    u64 d;
    asm("fma.rn.f32x2 %0, %1, %2, %3;" : "=l"(d) : "l"(a), "l"(b), "l"(c));
    return d;
}
__device__ __forceinline__ u64 packf2(float x, float y) {
    u64 p;
    asm("mov.b64 %0, {%1, %2};" : "=l"(p) : "f"(x), "f"(y));
    return p;
}
__device__ __forceinline__ float2 unpackf2(u64 p) {
    float2 r;
    asm("mov.b64 {%0, %1}, %2;" : "=f"(r.x), "=f"(r.y) : "l"(p));
    return r;
}

// ---------------------------------------------------------------------------
// 64x64x32-tiled fp32 GEMM, 128 threads, 8 rows x 4 cols per thread, f32x2.
// TRANS_W: C = X[M,K] @ W[N,K]^T ; else C = X[M,K] @ W[K,N]. +bias over N.
// smem k-major: XsT[32][68] ([kk][row]), Ws[32][68] ([kk][col]).
// ---------------------------------------------------------------------------
template <bool TRANS_W>
__global__ void __launch_bounds__(128) gemm64(
    const float* __restrict__ X, const float* __restrict__ W,
    const float* __restrict__ bias, float* __restrict__ C,
    int K, int N)
{
    __shared__ float XsT[32 * 68];
    __shared__ float Ws[32 * 68];
    const int tid = threadIdx.x;
    const int tx = tid & 15;        // -> 4 contiguous cols at tx*4
    const int ty = tid >> 4;        // 0..7 -> 8 rows at ty*8
    const int row0 = blockIdx.y * 64;
    const int col0 = blockIdx.x * 64;
    const int rot = tid & 3;

    u64 acc[4][4];
#pragma unroll
    for (int i = 0; i < 4; i++)
#pragma unroll
        for (int j = 0; j < 4; j++) acc[i][j] = 0ull;

    for (int k0 = 0; k0 < K; k0 += 32) {
        // X tile 64x32 -> XsT[kk][row] (transpose store, lane-rotated)
#pragma unroll
        for (int l = 0; l < 4; l++) {
            int idx = tid + l * 128;
            int r = idx >> 3, c = (idx & 7) * 4;
            float4 v = *(const float4*)(X + (size_t)(row0 + r) * K + k0 + c);
            float vv[4] = {v.x, v.y, v.z, v.w};
#pragma unroll
            for (int i = 0; i < 4; i++) {
                int ii = (i + rot) & 3;
                XsT[(c + ii) * 68 + r] = vv[ii];
            }
        }
        if (TRANS_W) {
#pragma unroll
            for (int l = 0; l < 4; l++) {
                int idx = tid + l * 128;
                int r = idx >> 3, c = (idx & 7) * 4;   // r: col, c: kk
                float4 v = *(const float4*)(W + (size_t)(col0 + r) * K + k0 + c);
                float vv[4] = {v.x, v.y, v.z, v.w};
#pragma unroll
                for (int i = 0; i < 4; i++) {
                    int ii = (i + rot) & 3;
                    Ws[(c + ii) * 68 + r] = vv[ii];
                }
            }
        } else {
#pragma unroll
            for (int l = 0; l < 4; l++) {
                int idx = tid + l * 128;
                int r = idx >> 4, c = (idx & 15) * 4;  // r: kk, c: col
                float4 v = *(const float4*)(W + (size_t)(k0 + r) * N + col0 + c);
                *(float4*)&Ws[r * 68 + c] = v;
            }
        }
        __syncthreads();
#pragma unroll
        for (int kk = 0; kk < 32; kk++) {
            ulonglong2 aA = *(const ulonglong2*)(XsT + kk * 68 + ty * 8);
            ulonglong2 aB = *(const ulonglong2*)(XsT + kk * 68 + ty * 8 + 4);
            float4 b4 = *(const float4*)(Ws + kk * 68 + tx * 4);
            u64 b0 = packf2(b4.x, b4.x), b1 = packf2(b4.y, b4.y);
            u64 b2 = packf2(b4.z, b4.z), b3 = packf2(b4.w, b4.w);
            acc[0][0] = ffma2(aA.x, b0, acc[0][0]);
            acc[0][1] = ffma2(aA.x, b1, acc[0][1]);
            acc[0][2] = ffma2(aA.x, b2, acc[0][2]);
            acc[0][3] = ffma2(aA.x, b3, acc[0][3]);
            acc[1][0] = ffma2(aA.y, b0, acc[1][0]);
            acc[1][1] = ffma2(aA.y, b1, acc[1][1]);
            acc[1][2] = ffma2(aA.y, b2, acc[1][2]);
            acc[1][3] = ffma2(aA.y, b3, acc[1][3]);
            acc[2][0] = ffma2(aB.x, b0, acc[2][0]);
            acc[2][1] = ffma2(aB.x, b1, acc[2][1]);
            acc[2][2] = ffma2(aB.x, b2, acc[2][2]);
            acc[2][3] = ffma2(aB.x, b3, acc[2][3]);
            acc[3][0] = ffma2(aB.y, b0, acc[3][0]);
            acc[3][1] = ffma2(aB.y, b1, acc[3][1]);
            acc[3][2] = ffma2(aB.y, b2, acc[3][2]);
            acc[3][3] = ffma2(aB.y, b3, acc[3][3]);
        }
        __syncthreads();
    }

    float4 bv;
    if (bias) bv = *(const float4*)&bias[col0 + tx * 4];
    else { bv.x = bv.y = bv.z = bv.w = 0.f; }
#pragma unroll
    for (int i2 = 0; i2 < 4; i2++) {
        float2 p0 = unpackf2(acc[i2][0]);
        float2 p1 = unpackf2(acc[i2][1]);
        float2 p2 = unpackf2(acc[i2][2]);
        float2 p3 = unpackf2(acc[i2][3]);
        float4 oA, oB;
        oA.x = p0.x + bv.x; oA.y = p1.x + bv.y; oA.z = p2.x + bv.z; oA.w = p3.x + bv.w;
        oB.x = p0.y + bv.x; oB.y = p1.y + bv.y; oB.z = p2.y + bv.z; oB.w = p3.y + bv.w;
        *(float4*)&C[(size_t)(row0 + ty * 8 + 2 * i2 + 0) * N + col0 + tx * 4] = oA;
        *(float4*)&C[(size_t)(row0 + ty * 8 + 2 * i2 + 1) * N + col0 + tx * 4] = oB;
    }
}

// s[i] = phi[i,:] . b_psi
__global__ void __launch_bounds__(256) dot_s_kernel(const float* __restrict__ phi,
                                                    const float* __restrict__ bpsi,
                                                    float* __restrict__ s)
{
    int i = blockIdx.x;
    float p = 0.f;
    for (int a = threadIdx.x; a < A_DIM; a += 256)
        p += phi[(size_t)i * A_DIM + a] * bpsi[a];
    __shared__ float r[8];
#pragma unroll
    for (int o = 16; o; o >>= 1) p += __shfl_down_sync(0xffffffffu, p, o);
    if ((threadIdx.x & 31) == 0) r[threadIdx.x >> 5] = p;
    __syncthreads();
    if (threadIdx.x == 0) {
        float t = 0.f;
#pragma unroll
        for (int w = 0; w < 8; w++) t += r[w];
        s[i] = t;
    }
}

// ---------------------------------------------------------------------------
// Fused attention chunk. 256 threads, f32x2 micro-kernel, vectorized LDS.
// Dynamic smem (floats):
//  [0,16896)  phase1: hsT[32][132] @0, Msk[32][68] @4224 ; phase2: hs2[128][132]
//  [16896,25600) ps[128][68]   (p[t][q], q contiguous)
//  [25600,26688) red[64][17]
//  [26688,26752) sv[64]
// ---------------------------------------------------------------------------
#define SMEM_FLOATS 26752
#define ATTN_SMEM_BYTES (SMEM_FLOATS * 4)

__global__ void __launch_bounds__(256, 2) attn_chunk_kernel(
    const float* __restrict__ h_enc)
{
    const int split = blockIdx.x;
    const int b = blockIdx.y;
    const int t0 = split * TCHUNK;
    const int tid = threadIdx.x;
    const int tx = tid & 15;    // phase1: q quad tx*4 ; phase2: h lanes
    const int ty = tid >> 4;    // phase1: 8 t rows   ; phase2: q quad ty*4

    extern __shared__ float sm[];
    float* hsT = sm;                 // [32][132]
    float* Msk = sm + 32 * 132;      // [32][68]
    float* hs2 = sm;                 // [128][132]
    float* ps  = sm + 16896;         // [128][68]
    float* red = sm + 25600;         // [64][17]
    float* sv  = sm + 26688;         // [64]

    const float* hb = h_enc + ((size_t)b * T_DIM + t0) * H_DIM;

    if (tid < 64) sv[tid] = g_s[tid * B_DIM + b];

    // -------- Phase 1: e[128 t][64 q] = h_tile @ M_b^T --------
    u64 acc[4][4];
#pragma unroll
    for (int i = 0; i < 4; i++)
#pragma unroll
        for (int j = 0; j < 4; j++) acc[i][j] = 0ull;

    const int rot = tid & 3;
    for (int k0 = 0; k0 < H_DIM; k0 += 32) {
        // h tile 128x32 -> hsT[kk][t] (transpose, lane-rotated)
#pragma unroll
        for (int l = 0; l < 4; l++) {
            int idx = tid + l * 256;
            int r = idx >> 3, c = (idx & 7) * 4;
            float4 v = *(const float4*)(hb + (size_t)r * H_DIM + k0 + c);
            float vv[4] = {v.x, v.y, v.z, v.w};
#pragma unroll
            for (int i = 0; i < 4; i++) {
                int ii = (i + rot) & 3;
                hsT[(c + ii) * 132 + r] = vv[ii];
            }
        }
        // M tile 64q x 32kk -> Msk[kk][q]
        {
            int q = tid >> 2, kb = (tid & 3) * 8;
            const float* mp = g_M + (size_t)(q * B_DIM + b) * H_DIM + k0 + kb;
            float4 v0 = *(const float4*)mp;
            float4 v1 = *(const float4*)(mp + 4);
            float mv[8] = {v0.x, v0.y, v0.z, v0.w, v1.x, v1.y, v1.z, v1.w};
            int r8 = tid & 7;
#pragma unroll
            for (int i = 0; i < 8; i++) {
                int ii = (i + r8) & 7;
                Msk[(kb + ii) * 68 + q] = mv[ii];
            }
        }
        __syncthreads();
#pragma unroll
        for (int kk = 0; kk < 32; kk++) {
            ulonglong2 aA = *(const ulonglong2*)(hsT + kk * 132 + ty * 8);
            ulonglong2 aB = *(const ulonglong2*)(hsT + kk * 132 + ty * 8 + 4);
            float4 b4 = *(const float4*)(Msk + kk * 68 + tx * 4);
            u64 b0 = packf2(b4.x, b4.x), b1 = packf2(b4.y, b4.y);
            u64 b2 = packf2(b4.z, b4.z), b3 = packf2(b4.w, b4.w);
            acc[0][0] = ffma2(aA.x, b0, acc[0][0]);
            acc[0][1] = ffma2(aA.x, b1, acc[0][1]);
            acc[0][2] = ffma2(aA.x, b2, acc[0][2]);
            acc[0][3] = ffma2(aA.x, b3, acc[0][3]);
            acc[1][0] = ffma2(aA.y, b0, acc[1][0]);
            acc[1][1] = ffma2(aA.y, b1, acc[1][1]);
            acc[1][2] = ffma2(aA.y, b2, acc[1][2]);
            acc[1][3] = ffma2(aA.y, b3, acc[1][3]);
            acc[2][0] = ffma2(aB.x, b0, acc[2][0]);
            acc[2][1] = ffma2(aB.x, b1, acc[2][1]);
            acc[2][2] = ffma2(aB.x, b2, acc[2][2]);
            acc[2][3] = ffma2(aB.x, b3, acc[2][3]);
            acc[3][0] = ffma2(aB.y, b0, acc[3][0]);
            acc[3][1] = ffma2(aB.y, b1, acc[3][1]);
            acc[3][2] = ffma2(aB.y, b2, acc[3][2]);
            acc[3][3] = ffma2(aB.y, b3, acc[3][3]);
        }
        __syncthreads();
    }

    // Unpack e[8 t][4 q] (t = ty*8+i, q = tx*4+j)
    float e[8][4];
#pragma unroll
    for (int i2 = 0; i2 < 4; i2++)
#pragma unroll
        for (int j = 0; j < 4; j++) {
            float2 t = unpackf2(acc[i2][j]);
            e[2 * i2 + 0][j] = t.x;
            e[2 * i2 + 1][j] = t.y;
        }

    // bias + local max per q
#pragma unroll
    for (int j = 0; j < 4; j++) {
        int q = tx * 4 + j;
        float sb = sv[q];
        float mloc = -1e30f;
#pragma unroll
        for (int i = 0; i < 8; i++) {
            e[i][j] += sb;
            mloc = fmaxf(mloc, e[i][j]);
        }
        red[q * 17 + ty] = mloc;
    }
    __syncthreads();
    if (tid < 64) {
        float m = -1e30f;
#pragma unroll
        for (int w = 0; w < 16; w++) m = fmaxf(m, red[tid * 17 + w]);
        sv[tid] = m;   // per-q chunk max
    }
    __syncthreads();

    float m[4];
#pragma unroll
    for (int j = 0; j < 4; j++) m[j] = sv[tx * 4 + j];
    float ls[4] = {0.f, 0.f, 0.f, 0.f};
#pragma unroll
    for (int i = 0; i < 8; i++) {
        float4 pv;
        pv.x = __expf(e[i][0] - m[0]); ls[0] += pv.x;
        pv.y = __expf(e[i][1] - m[1]); ls[1] += pv.y;
        pv.z = __expf(e[i][2] - m[2]); ls[2] += pv.z;
        pv.w = __expf(e[i][3] - m[3]); ls[3] += pv.w;
        *(float4*)&ps[(ty * 8 + i) * 68 + tx * 4] = pv;
    }
#pragma unroll
    for (int j = 0; j < 4; j++) red[(tx * 4 + j) * 17 + ty] = ls[j];
    __syncthreads();
    if (tid < 64) {
        float l = 0.f;
#pragma unroll
        for (int w = 0; w < 16; w++) l += red[tid * 17 + w];
        int base = (b * SPLITS + split) * Q_DIM + tid;
        g_lpart[base] = l;
        g_mpart[base] = sv[tid];
    }

    // -------- Phase 2: c_part[64 q][1024 h] = p^T @ h_tile --------
    float* cp = g_cpart + (size_t)(b * SPLITS + split) * Q_DIM * H_DIM;
    for (int h0 = 0; h0 < H_DIM; h0 += 128) {
        __syncthreads();
        // hs2[128 t][132] : direct float4 stores (no transpose)
#pragma unroll
        for (int l = 0; l < 16; l++) {
            int idx = tid + l * 256;
            int r = idx >> 5, c = (idx & 31) * 4;
            float4 v = *(const float4*)(hb + (size_t)r * H_DIM + h0 + c);
            *(float4*)(hs2 + r * 132 + c) = v;
        }
        __syncthreads();

        u64 c2[4][4];   // [j: q][u2: h pairs (0,1)->tx*4.., (2,3)->64+tx*4..]
#pragma unroll
        for (int j = 0; j < 4; j++)
#pragma unroll
            for (int u = 0; u < 4; u++) c2[j][u] = 0ull;

#pragma unroll 8
        for (int kk = 0; kk < 128; kk++) {
            float4 a4 = *(const float4*)(ps + kk * 68 + ty * 4);
            ulonglong2 bA = *(const ulonglong2*)(hs2 + kk * 132 + tx * 4);
            ulonglong2 bB = *(const ulonglong2*)(hs2 + kk * 132 + 64 + tx * 4);
            u64 a0 = packf2(a4.x, a4.x), a1 = packf2(a4.y, a4.y);
            u64 a2 = packf2(a4.z, a4.z), a3 = packf2(a4.w, a4.w);
            c2[0][0] = ffma2(a0, bA.x, c2[0][0]);
            c2[0][1] = ffma2(a0, bA.y, c2[0][1]);
            c2[0][2] = ffma2(a0, bB.x, c2[0][2]);
            c2[0][3] = ffma2(a0, bB.y, c2[0][3]);
            c2[1][0] = ffma2(a1, bA.x, c2[1][0]);
            c2[1][1] = ffma2(a1, bA.y, c2[1][1]);
            c2[1][2] = ffma2(a1, bB.x, c2[1][2]);
            c2[1][3] = ffma2(a1, bB.y, c2[1][3]);
            c2[2][0] = ffma2(a2, bA.x, c2[2][0]);
            c2[2][1] = ffma2(a2, bA.y, c2[2][1]);
            c2[2][2] = ffma2(a2, bB.x, c2[2][2]);
            c2[2][3] = ffma2(a2, bB.y, c2[2][3]);
            c2[3][0] = ffma2(a3, bA.x, c2[3][0]);
            c2[3][1] = ffma2(a3, bA.y, c2[3][1]);
            c2[3][2] = ffma2(a3, bB.x, c2[3][2]);
            c2[3][3] = ffma2(a3, bB.y, c2[3][3]);
        }
#pragma unroll
        for (int j = 0; j < 4; j++) {
            int q = ty * 4 + j;
            float2 p0 = unpackf2(c2[j][0]);
            float2 p1 = unpackf2(c2[j][1]);
            float4 oA; oA.x = p0.x; oA.y = p0.y; oA.z = p1.x; oA.w = p1.y;
            *(float4*)&cp[(size_t)q * H_DIM + h0 + tx * 4] = oA;
            float2 p2 = unpackf2(c2[j][2]);
            float2 p3 = unpackf2(c2[j][3]);
            float4 oB; oB.x = p2.x; oB.y = p2.y; oB.z = p3.x; oB.w = p3.y;
            *(float4*)&cp[(size_t)q * H_DIM + h0 + 64 + tx * 4] = oB;
        }
    }
}

// Combine split partials
__global__ void __launch_bounds__(256) combine_kernel(float* __restrict__ out)
{
    const int q = blockIdx.x;
    const int b = blockIdx.y;
    const int tid = threadIdx.x;

    float m = -1e30f;
#pragma unroll
    for (int sI = 0; sI < SPLITS; sI++)
        m = fmaxf(m, g_mpart[(b * SPLITS + sI) * Q_DIM + q]);
    float w[SPLITS];
    float l = 0.f;
#pragma unroll
    for (int sI = 0; sI < SPLITS; sI++) {
        float ws = __expf(g_mpart[(b * SPLITS + sI) * Q_DIM + q] - m);
        w[sI] = ws;
        l += ws * g_lpart[(b * SPLITS + sI) * Q_DIM + q];
    }
    float inv = 1.0f / l;

    for (int h = tid; h < H_DIM; h += 256) {
        float acc = 0.f;
#pragma unroll
        for (int sI = 0; sI < SPLITS; sI++)
            acc += w[sI] * g_cpart[((size_t)(b * SPLITS + sI) * Q_DIM + q) * H_DIM + h];
        out[((size_t)(b * Q_DIM + q)) * H_DIM + h] = acc * inv;
    }
}

// ---------------------------------------------------------------------------
extern "C" void kernel_launch(void* const* d_in, const int* in_sizes, int n_in,
                              void* d_out, int out_size)
{
    (void)in_sizes; (void)n_in; (void)out_size;
    const float* h_enc = (const float*)d_in[0];
    const float* h_dec = (const float*)d_in[1];
    const float* W_psi = (const float*)d_in[2];
    const float* b_psi = (const float*)d_in[3];
    const float* W_phi = (const float*)d_in[4];
    const float* b_phi = (const float*)d_in[5];
    float* out = (float*)d_out;

    float *phi, *Mmat, *s;
    cudaGetSymbolAddress((void**)&phi, g_phi);
    cudaGetSymbolAddress((void**)&Mmat, g_M);
    cudaGetSymbolAddress((void**)&s, g_s);

    // phi = h_dec @ W_phi^T + b_phi   (NT)
    gemm64<true><<<dim3(16, 16), 128>>>(h_dec, W_phi, b_phi, phi, H_DIM, A_DIM);
    // M = phi @ W_psi                 (NN)
    gemm64<false><<<dim3(16, 16), 128>>>(phi, W_psi, nullptr, Mmat, A_DIM, H_DIM);
    // s = phi @ b_psi
    dot_s_kernel<<<QB_DIM, 256>>>(phi, b_psi, s);

    // Fused split-T attention
    cudaFuncSetAttribute(attn_chunk_kernel,
                         cudaFuncAttributeMaxDynamicSharedMemorySize,
                         ATTN_SMEM_BYTES);
    attn_chunk_kernel<<<dim3(SPLITS, B_DIM), 256, ATTN_SMEM_BYTES>>>(h_enc);

    // Combine partials
    combine_kernel<<<dim3(Q_DIM, B_DIM), 256>>>(out);
}